// round 7
// baseline (speedup 1.0000x reference)
#include <cuda_runtime.h>
#include <cuda_bf16.h>
#include <math.h>
#include <stdint.h>

#define SEQ   2048
#define ND    1024
#define NH    16
#define DH    64
#define NPOS  64
#define QT    16      // q rows per fused CTA

typedef __nv_bfloat16 bf16;
typedef __nv_bfloat162 bf162;

// ---------------- scratch (device globals: allocation-free) ----------------
__device__ float g_Q[SEQ * ND];                       // fp32 Q (li_kernel)
__device__ float g_li[NH * SEQ * NPOS];

__device__ bf16 g_inqh[SEQ * ND], g_inql[SEQ * ND];
__device__ bf16 g_inkh[SEQ * ND], g_inkl[SEQ * ND];
__device__ bf16 g_invh[SEQ * ND], g_invl[SEQ * ND];
__device__ bf16 g_wqh[ND * ND], g_wql[ND * ND];
__device__ bf16 g_wkh[ND * ND], g_wkl[ND * ND];
__device__ bf16 g_wvh[ND * ND], g_wvl[ND * ND];
__device__ bf16 g_woh[ND * ND], g_wol[ND * ND];
__device__ bf16 g_Qh[SEQ * ND], g_Ql[SEQ * ND];
__device__ bf16 g_Kh[SEQ * ND], g_Kl[SEQ * ND];
__device__ bf16 g_Vh[SEQ * ND], g_Vl[SEQ * ND];
__device__ bf16 g_ctxh[SEQ * ND], g_ctxl[SEQ * ND];

// ---------------- PTX helpers ----------------------------------------------
__device__ __forceinline__ uint32_t smem_u32(const void* p) {
    return (uint32_t)__cvta_generic_to_shared(p);
}
__device__ __forceinline__ void ldsm4(uint32_t* r, uint32_t a) {
    asm volatile("ldmatrix.sync.aligned.m8n8.x4.shared.b16 {%0,%1,%2,%3}, [%4];"
                 : "=r"(r[0]), "=r"(r[1]), "=r"(r[2]), "=r"(r[3]) : "r"(a));
}
__device__ __forceinline__ void ldsm2t(uint32_t* r, uint32_t a) {
    asm volatile("ldmatrix.sync.aligned.m8n8.x2.trans.shared.b16 {%0,%1}, [%2];"
                 : "=r"(r[0]), "=r"(r[1]) : "r"(a));
}
__device__ __forceinline__ void mma16816(float* c, const uint32_t* a, const uint32_t* b) {
    asm volatile(
        "mma.sync.aligned.m16n8k16.row.col.f32.bf16.bf16.f32 "
        "{%0,%1,%2,%3}, {%4,%5,%6,%7}, {%8,%9}, {%0,%1,%2,%3};"
        : "+f"(c[0]), "+f"(c[1]), "+f"(c[2]), "+f"(c[3])
        : "r"(a[0]), "r"(a[1]), "r"(a[2]), "r"(a[3]), "r"(b[0]), "r"(b[1]));
}

// ---------------- split fp32 -> bf16 hi + bf16 lo ---------------------------
__global__ __launch_bounds__(256) void split_kernel(
    const float* __restrict__ s, bf16* __restrict__ hi, bf16* __restrict__ lo)
{
    int i = (blockIdx.x * 256 + threadIdx.x) * 4;
    float4 v = *(const float4*)&s[i];
    bf16 h0 = __float2bfloat16_rn(v.x), h1 = __float2bfloat16_rn(v.y);
    bf16 h2 = __float2bfloat16_rn(v.z), h3 = __float2bfloat16_rn(v.w);
    bf16 l0 = __float2bfloat16_rn(v.x - __bfloat162float(h0));
    bf16 l1 = __float2bfloat16_rn(v.y - __bfloat162float(h1));
    bf16 l2 = __float2bfloat16_rn(v.z - __bfloat162float(h2));
    bf16 l3 = __float2bfloat16_rn(v.w - __bfloat162float(h3));
    *(bf162*)&hi[i]     = bf162{h0, h1};
    *(bf162*)&hi[i + 2] = bf162{h2, h3};
    *(bf162*)&lo[i]     = bf162{l0, l1};
    *(bf162*)&lo[i + 2] = bf162{l2, l3};
}

// ---------------- Y = X @ W^T + bias (split-bf16 MMA) -----------------------
#define KST 40   // 32 + 8 pad

__global__ __launch_bounds__(256, 2) void mm_bias_kernel(
    const bf16* __restrict__ Xh, const bf16* __restrict__ Xl,
    const bf16* __restrict__ Wh, const bf16* __restrict__ Wl,
    const float* __restrict__ bias,
    float* __restrict__ Yf, bf16* __restrict__ Yh, bf16* __restrict__ Yl)
{
    __shared__ bf16 Xsh[128][KST], Xsl[128][KST];
    __shared__ bf16 Wsh[64][KST],  Wsl[64][KST];
    const int tid = threadIdx.x, lane = tid & 31, warp = tid >> 5;
    const int wm = warp & 3, wn = warp >> 2;
    const int m0 = blockIdx.y * 128, n0 = blockIdx.x * 64;

    const int xr = tid >> 2, xc = (tid & 3) * 8;

    float acc[2][4][4] = {};
    for (int kt = 0; kt < ND; kt += 32) {
        *(uint4*)&Xsh[xr][xc]      = *(const uint4*)&Xh[(size_t)(m0 + xr) * ND + kt + xc];
        *(uint4*)&Xsh[xr + 64][xc] = *(const uint4*)&Xh[(size_t)(m0 + xr + 64) * ND + kt + xc];
        *(uint4*)&Xsl[xr][xc]      = *(const uint4*)&Xl[(size_t)(m0 + xr) * ND + kt + xc];
        *(uint4*)&Xsl[xr + 64][xc] = *(const uint4*)&Xl[(size_t)(m0 + xr + 64) * ND + kt + xc];
        *(uint4*)&Wsh[xr][xc]      = *(const uint4*)&Wh[(size_t)(n0 + xr) * ND + kt + xc];
        *(uint4*)&Wsl[xr][xc]      = *(const uint4*)&Wl[(size_t)(n0 + xr) * ND + kt + xc];
        __syncthreads();
        #pragma unroll
        for (int kk = 0; kk < 32; kk += 16) {
            uint32_t Ah[2][4], Al[2][4], Bh[4][2], Bl[4][2];
            int arow = wm * 32 + (lane & 7) + ((lane >> 3) & 1) * 8;
            int acol = kk + (lane >> 4) * 8;
            ldsm4(Ah[0], smem_u32(&Xsh[arow][acol]));
            ldsm4(Ah[1], smem_u32(&Xsh[arow + 16][acol]));
            ldsm4(Al[0], smem_u32(&Xsl[arow][acol]));
            ldsm4(Al[1], smem_u32(&Xsl[arow + 16][acol]));
            int brow = wn * 32 + (lane >> 4) * 8 + (lane & 7);
            int bcol = kk + ((lane >> 3) & 1) * 8;
            ldsm4(&Bh[0][0], smem_u32(&Wsh[brow][bcol]));
            ldsm4(&Bh[2][0], smem_u32(&Wsh[brow + 16][bcol]));
            ldsm4(&Bl[0][0], smem_u32(&Wsl[brow][bcol]));
            ldsm4(&Bl[2][0], smem_u32(&Wsl[brow + 16][bcol]));
            #pragma unroll
            for (int mt = 0; mt < 2; mt++)
                #pragma unroll
                for (int nt = 0; nt < 4; nt++) {
                    mma16816(acc[mt][nt], Ah[mt], Bh[nt]);
                    mma16816(acc[mt][nt], Ah[mt], Bl[nt]);
                    mma16816(acc[mt][nt], Al[mt], Bh[nt]);
                }
        }
        __syncthreads();
    }
    const int r0 = lane >> 2, cc = (lane & 3) * 2;
    #pragma unroll
    for (int mt = 0; mt < 2; mt++)
        #pragma unroll
        for (int nt = 0; nt < 4; nt++) {
            int m = m0 + wm * 32 + mt * 16 + r0;
            int n = n0 + wn * 32 + nt * 8 + cc;
            float b0 = bias[n], b1 = bias[n + 1];
            float v0 = acc[mt][nt][0] + b0, v1 = acc[mt][nt][1] + b1;
            float v2 = acc[mt][nt][2] + b0, v3 = acc[mt][nt][3] + b1;
            if (Yf) {
                *(float2*)&Yf[(size_t)m * ND + n]       = float2{v0, v1};
                *(float2*)&Yf[(size_t)(m + 8) * ND + n] = float2{v2, v3};
            }
            if (Yh) {
                bf16 h0 = __float2bfloat16_rn(v0), h1 = __float2bfloat16_rn(v1);
                bf16 h2 = __float2bfloat16_rn(v2), h3 = __float2bfloat16_rn(v3);
                *(bf162*)&Yh[(size_t)m * ND + n]       = bf162{h0, h1};
                *(bf162*)&Yh[(size_t)(m + 8) * ND + n] = bf162{h2, h3};
                *(bf162*)&Yl[(size_t)m * ND + n] =
                    bf162{__float2bfloat16_rn(v0 - __bfloat162float(h0)),
                          __float2bfloat16_rn(v1 - __bfloat162float(h1))};
                *(bf162*)&Yl[(size_t)(m + 8) * ND + n] =
                    bf162{__float2bfloat16_rn(v2 - __bfloat162float(h2)),
                          __float2bfloat16_rn(v3 - __bfloat162float(h3))};
            }
        }
}

// -------- li[h,q,n] = sum_d Q[q, h*64+d] * pos_emb[d, n] --------------------
__global__ __launch_bounds__(256) void li_kernel(const float* __restrict__ pos_emb)
{
    __shared__ float Qs[64][65];
    __shared__ float Ps[64][65];
    const int tid = threadIdx.x;
    const int tx = tid & 15, ty = tid >> 4;
    const int h = blockIdx.y;
    const int q0 = blockIdx.x * 64;

    for (int i = tid; i < 64 * 64; i += 256) {
        int r = i >> 6, c = i & 63;
        Qs[r][c] = g_Q[(q0 + r) * ND + h * DH + c];
        Ps[r][c] = pos_emb[r * NPOS + c];
    }
    __syncthreads();

    float acc[4][4] = {};
    #pragma unroll 8
    for (int d = 0; d < 64; d++) {
        float a[4], b[4];
        #pragma unroll
        for (int i = 0; i < 4; i++) a[i] = Qs[ty * 4 + i][d];
        #pragma unroll
        for (int j = 0; j < 4; j++) b[j] = Ps[d][tx * 4 + j];
        #pragma unroll
        for (int i = 0; i < 4; i++)
            #pragma unroll
            for (int j = 0; j < 4; j++) acc[i][j] += a[i] * b[j];
    }
    #pragma unroll
    for (int i = 0; i < 4; i++)
        #pragma unroll
        for (int j = 0; j < 4; j++)
            g_li[(h * SEQ + q0 + ty * 4 + i) * NPOS + tx * 4 + j] = acc[i][j];
}

// ================= fused attention: QK^T -> CoPE -> softmax -> P·V ==========
// One CTA = 16 q-rows of one head. 256 threads / 8 warps.
#define LSS 2052          // logits smem row stride (floats); %32 banks = +4/row
#define KSS 72            // K/V tile row stride (bf16)
#define SSS 136           // score tile row stride (bf16)

#define OFF_LS  0
#define OFF_KH  (OFF_LS + QT * LSS * 4)          // 131328
#define OFF_KL  (OFF_KH + 128 * KSS * 2)         // +18432
#define OFF_QH  (OFF_KL + 128 * KSS * 2)
#define OFF_QL  (OFF_QH + QT * KSS * 2)
#define OFF_SH  (OFF_QL + QT * KSS * 2)
#define OFF_SL  (OFF_SH + QT * SSS * 2)
#define OFF_LI  (OFF_SL + QT * SSS * 2)
#define OFF_INV (OFF_LI + QT * 64 * 4)
#define FUSED_SMEM (OFF_INV + QT * 4)

__global__ __launch_bounds__(256, 1) void fused_attn_kernel()
{
    extern __shared__ char sm[];
    float* Ls    = (float*)(sm + OFF_LS);
    bf16*  Ksh   = (bf16*)(sm + OFF_KH);
    bf16*  Ksl   = (bf16*)(sm + OFF_KL);
    bf16*  Qsh   = (bf16*)(sm + OFF_QH);
    bf16*  Qsl   = (bf16*)(sm + OFF_QL);
    bf16*  Ssh   = (bf16*)(sm + OFF_SH);
    bf16*  Ssl   = (bf16*)(sm + OFF_SL);
    float* lis   = (float*)(sm + OFF_LI);
    float* rinv  = (float*)(sm + OFF_INV);

    const int tid = threadIdx.x, lane = tid & 31, warp = tid >> 5;
    const int h = blockIdx.y;
    const int q0 = blockIdx.x * QT;
    const int ho = h * DH;

    // ---- phase 1: load Q tile + li rows ----
    if (tid < 128) {
        int r = tid >> 3, c = (tid & 7) * 8;
        *(uint4*)&Qsh[r * KSS + c] = *(const uint4*)&g_Qh[(size_t)(q0 + r) * ND + ho + c];
        *(uint4*)&Qsl[r * KSS + c] = *(const uint4*)&g_Ql[(size_t)(q0 + r) * ND + ho + c];
    }
    for (int i = tid; i < QT * 64; i += 256) {
        int r = i >> 6, n = i & 63;
        lis[r * 64 + n] = g_li[(h * SEQ + q0 + r) * NPOS + n];
    }
    __syncthreads();

    // Q A-fragments (shared by all warps, whole DH=64)
    uint32_t QAh[4][4], QAl[4][4];
    {
        int arow = (lane & 7) + ((lane >> 3) & 1) * 8;
        int acol = (lane >> 4) * 8;
        #pragma unroll
        for (int s = 0; s < 4; s++) {
            ldsm4(QAh[s], smem_u32(&Qsh[arow * KSS + s * 16 + acol]));
            ldsm4(QAl[s], smem_u32(&Qsl[arow * KSS + s * 16 + acol]));
        }
    }

    const int ldr = tid >> 1, ldc = (tid & 1) * 32;   // K/V cooperative loader

    // ---- phase 2: logits = 0.125 * Q K^T -> Ls ----
    for (int kt = 0; kt < 16; kt++) {
        __syncthreads();   // prev chunk's MMA reads done
        #pragma unroll
        for (int i = 0; i < 4; i++) {
            *(uint4*)&Ksh[ldr * KSS + ldc + i * 8] =
                *(const uint4*)&g_Kh[(size_t)(kt * 128 + ldr) * ND + ho + ldc + i * 8];
            *(uint4*)&Ksl[ldr * KSS + ldc + i * 8] =
                *(const uint4*)&g_Kl[(size_t)(kt * 128 + ldr) * ND + ho + ldc + i * 8];
        }
        __syncthreads();

        float acc[2][4] = {};
        int brow = warp * 16 + (lane >> 4) * 8 + (lane & 7);
        #pragma unroll
        for (int s = 0; s < 4; s++) {
            uint32_t Bh[4], Bl[4];
            int bcol = s * 16 + ((lane >> 3) & 1) * 8;
            ldsm4(Bh, smem_u32(&Ksh[brow * KSS + bcol]));
            ldsm4(Bl, smem_u32(&Ksl[brow * KSS + bcol]));
            #pragma unroll
            for (int nt = 0; nt < 2; nt++) {
                mma16816(acc[nt], QAh[s], &Bh[nt * 2]);
                mma16816(acc[nt], QAh[s], &Bl[nt * 2]);
                mma16816(acc[nt], QAl[s], &Bh[nt * 2]);
            }
        }
        int r = lane >> 2, cbase = kt * 128 + warp * 16 + (lane & 3) * 2;
        #pragma unroll
        for (int nt = 0; nt < 2; nt++) {
            int c = cbase + nt * 8;
            *(float2*)&Ls[r * LSS + c]       = float2{acc[nt][0] * 0.125f, acc[nt][1] * 0.125f};
            *(float2*)&Ls[(r + 8) * LSS + c] = float2{acc[nt][2] * 0.125f, acc[nt][3] * 0.125f};
        }
    }
    __syncthreads();

    // ---- phase 3: CoPE + softmax, per warp: rows 2w, 2w+1 ----
    for (int rr = 0; rr < 2; rr++) {
        const int row = warp * 2 + rr;
        float* lr = &Ls[row * LSS];
        const float* lirow = &lis[row * 64];

        // pass 1: gates (packed bf16), quad sums, per-segment warp suffix scans
        uint32_t gpk[16][2];
        float off[16], total[16];
        #pragma unroll
        for (int u = 0; u < 16; u++) {
            float4 lv = *(const float4*)&lr[u * 128 + lane * 4];
            float t0, t1, t2, t3;
            asm("tanh.approx.f32 %0, %1;" : "=f"(t0) : "f"(lv.x * 0.5f));
            asm("tanh.approx.f32 %0, %1;" : "=f"(t1) : "f"(lv.y * 0.5f));
            asm("tanh.approx.f32 %0, %1;" : "=f"(t2) : "f"(lv.z * 0.5f));
            asm("tanh.approx.f32 %0, %1;" : "=f"(t3) : "f"(lv.w * 0.5f));
            float g0 = fmaf(t0, 0.5f, 0.5f), g1 = fmaf(t1, 0.5f, 0.5f);
            float g2 = fmaf(t2, 0.5f, 0.5f), g3 = fmaf(t3, 0.5f, 0.5f);
            bf162 p0{__float2bfloat16_rn(g0), __float2bfloat16_rn(g1)};
            bf162 p1{__float2bfloat16_rn(g2), __float2bfloat16_rn(g3)};
            gpk[u][0] = *(uint32_t*)&p0;
            gpk[u][1] = *(uint32_t*)&p1;
            float qs = g0 + g1 + g2 + g3;
            // warp inclusive suffix scan of qs
            float s = qs;
            #pragma unroll
            for (int d = 1; d < 32; d <<= 1) {
                float n = __shfl_down_sync(0xffffffffu, s, d);
                if (lane < 32 - d) s += n;
            }
            off[u] = s - qs;                          // strictly-later lanes in segment
            total[u] = __shfl_sync(0xffffffffu, s, 0);
        }
        {   // add later-segment totals
            float run = 0.0f;
            #pragma unroll
            for (int u = 15; u >= 0; --u) { off[u] += run; run += total[u]; }
        }

        // pass 2: CoPE interp, store x back, track max
        float lmax = -INFINITY;
        #pragma unroll
        for (int u = 0; u < 16; u++) {
            float4 lv = *(const float4*)&lr[u * 128 + lane * 4];
            bf162 p0 = *(bf162*)&gpk[u][0];
            bf162 p1 = *(bf162*)&gpk[u][1];
            float g0 = __bfloat162float(p0.x), g1 = __bfloat162float(p0.y);
            float g2 = __bfloat162float(p1.x), g3 = __bfloat162float(p1.y);
            float i3 = g3, i2 = i3 + g2, i1 = i2 + g1, i0 = i1 + g0;
            float xs[4] = {lv.x, lv.y, lv.z, lv.w};
            float is[4] = {i0, i1, i2, i3};
            #pragma unroll
            for (int j = 0; j < 4; j++) {
                float pos = fminf(is[j] + off[u], (float)(NPOS - 1));
                float pf = floorf(pos);
                int fi = (int)pf;
                int ci = (int)ceilf(pos);
                float w = pos - pf;
                xs[j] += lirow[ci] * w + lirow[fi] * (1.0f - w);
                lmax = fmaxf(lmax, xs[j]);
            }
            *(float4*)&lr[u * 128 + lane * 4] = float4{xs[0], xs[1], xs[2], xs[3]};
        }
        #pragma unroll
        for (int d = 16; d > 0; d >>= 1)
            lmax = fmaxf(lmax, __shfl_xor_sync(0xffffffffu, lmax, d));

        // pass 3: exp, store unnormalized, sum
        float lsum = 0.0f;
        #pragma unroll
        for (int u = 0; u < 16; u++) {
            float4 lv = *(const float4*)&lr[u * 128 + lane * 4];
            lv.x = __expf(lv.x - lmax); lv.y = __expf(lv.y - lmax);
            lv.z = __expf(lv.z - lmax); lv.w = __expf(lv.w - lmax);
            lsum += lv.x + lv.y + lv.z + lv.w;
            *(float4*)&lr[u * 128 + lane * 4] = lv;
        }
        #pragma unroll
        for (int d = 16; d > 0; d >>= 1)
            lsum += __shfl_xor_sync(0xffffffffu, lsum, d);
        if (lane == 0) rinv[row] = 1.0f / lsum;
    }

    // ---- phase 4: ctx = P V (normalize during bf16 conversion) ----
    const int sr = tid >> 4, sc0 = (tid & 15) * 8;    // score converter
    float acc4[4] = {};
    for (int kt = 0; kt < 16; kt++) {
        __syncthreads();   // phase-3 writes / prev MMA reads done
        #pragma unroll
        for (int i = 0; i < 4; i++) {
            *(uint4*)&Ksh[ldr * KSS + ldc + i * 8] =
                *(const uint4*)&g_Vh[(size_t)(kt * 128 + ldr) * ND + ho + ldc + i * 8];
            *(uint4*)&Ksl[ldr * KSS + ldc + i * 8] =
                *(const uint4*)&g_Vl[(size_t)(kt * 128 + ldr) * ND + ho + ldc + i * 8];
        }
        {
            float inv = rinv[sr];
            const float* src = &Ls[sr * LSS + kt * 128 + sc0];
            #pragma unroll
            for (int jp = 0; jp < 4; jp++) {
                float a = src[2 * jp] * inv, b = src[2 * jp + 1] * inv;
                bf16 ha = __float2bfloat16_rn(a), hb = __float2bfloat16_rn(b);
                *(bf162*)&Ssh[sr * SSS + sc0 + 2 * jp] = bf162{ha, hb};
                *(bf162*)&Ssl[sr * SSS + sc0 + 2 * jp] =
                    bf162{__float2bfloat16_rn(a - __bfloat162float(ha)),
                          __float2bfloat16_rn(b - __bfloat162float(hb))};
            }
        }
        __syncthreads();

        int arow = (lane & 7) + ((lane >> 3) & 1) * 8;
        int acolb = (lane >> 4) * 8;
        #pragma unroll
        for (int ks = 0; ks < 8; ks++) {
            uint32_t Ah[4], Al[4], Bh[2], Bl[2];
            ldsm4(Ah, smem_u32(&Ssh[arow * SSS + ks * 16 + acolb]));
            ldsm4(Al, smem_u32(&Ssl[arow * SSS + ks * 16 + acolb]));
            uint32_t ba = smem_u32(&Ksh[(ks * 16 + (lane & 15)) * KSS + warp * 8]);
            uint32_t bb = smem_u32(&Ksl[(ks * 16 + (lane & 15)) * KSS + warp * 8]);
            ldsm2t(Bh, ba);
            ldsm2t(Bl, bb);
            mma16816(acc4, Ah, Bh);
            mma16816(acc4, Ah, Bl);
            mma16816(acc4, Al, Bh);
        }
    }

    // ---- epilogue: ctx -> hi/lo bf16 ----
    {
        int r = lane >> 2, cc = (lane & 3) * 2;
        int m = q0 + r, n = ho + warp * 8 + cc;
        float v0 = acc4[0], v1 = acc4[1], v2 = acc4[2], v3 = acc4[3];
        bf16 h0 = __float2bfloat16_rn(v0), h1 = __float2bfloat16_rn(v1);
        bf16 h2 = __float2bfloat16_rn(v2), h3 = __float2bfloat16_rn(v3);
        *(bf162*)&g_ctxh[(size_t)m * ND + n]       = bf162{h0, h1};
        *(bf162*)&g_ctxh[(size_t)(m + 8) * ND + n] = bf162{h2, h3};
        *(bf162*)&g_ctxl[(size_t)m * ND + n] =
            bf162{__float2bfloat16_rn(v0 - __bfloat162float(h0)),
                  __float2bfloat16_rn(v1 - __bfloat162float(h1))};
        *(bf162*)&g_ctxl[(size_t)(m + 8) * ND + n] =
            bf162{__float2bfloat16_rn(v2 - __bfloat162float(h2)),
                  __float2bfloat16_rn(v3 - __bfloat162float(h3))};
    }
}

// ---------------------------------------------------------------------------
extern "C" void kernel_launch(void* const* d_in, const int* in_sizes, int n_in,
                              void* d_out, int out_size)
{
    const float* q      = (const float*)d_in[0];
    const float* k      = (const float*)d_in[1];
    const float* v      = (const float*)d_in[2];
    const float* Wq_w   = (const float*)d_in[3];
    const float* Wq_b   = (const float*)d_in[4];
    const float* Wk_w   = (const float*)d_in[5];
    const float* Wk_b   = (const float*)d_in[6];
    const float* Wv_w   = (const float*)d_in[7];
    const float* Wv_b   = (const float*)d_in[8];
    const float* Wo_w   = (const float*)d_in[9];
    const float* Wo_b   = (const float*)d_in[10];
    const float* pos_emb= (const float*)d_in[11];
    float* out = (float*)d_out;

    static bool attr_set = false;
    if (!attr_set) {
        cudaFuncSetAttribute(fused_attn_kernel,
                             cudaFuncAttributeMaxDynamicSharedMemorySize, FUSED_SMEM);
        attr_set = true;
    }

    bf16 *inqh, *inql, *inkh, *inkl, *invh, *invl;
    bf16 *wqh, *wql, *wkh, *wkl, *wvh, *wvl, *woh, *wol;
    bf16 *Qh, *Ql, *Kh, *Kl, *Vh, *Vl, *ctxh, *ctxl;
    float* Qf;
    cudaGetSymbolAddress((void**)&inqh, g_inqh); cudaGetSymbolAddress((void**)&inql, g_inql);
    cudaGetSymbolAddress((void**)&inkh, g_inkh); cudaGetSymbolAddress((void**)&inkl, g_inkl);
    cudaGetSymbolAddress((void**)&invh, g_invh); cudaGetSymbolAddress((void**)&invl, g_invl);
    cudaGetSymbolAddress((void**)&wqh, g_wqh);   cudaGetSymbolAddress((void**)&wql, g_wql);
    cudaGetSymbolAddress((void**)&wkh, g_wkh);   cudaGetSymbolAddress((void**)&wkl, g_wkl);
    cudaGetSymbolAddress((void**)&wvh, g_wvh);   cudaGetSymbolAddress((void**)&wvl, g_wvl);
    cudaGetSymbolAddress((void**)&woh, g_woh);   cudaGetSymbolAddress((void**)&wol, g_wol);
    cudaGetSymbolAddress((void**)&Qh, g_Qh);     cudaGetSymbolAddress((void**)&Ql, g_Ql);
    cudaGetSymbolAddress((void**)&Kh, g_Kh);     cudaGetSymbolAddress((void**)&Kl, g_Kl);
    cudaGetSymbolAddress((void**)&Vh, g_Vh);     cudaGetSymbolAddress((void**)&Vl, g_Vl);
    cudaGetSymbolAddress((void**)&ctxh, g_ctxh); cudaGetSymbolAddress((void**)&ctxl, g_ctxl);
    cudaGetSymbolAddress((void**)&Qf, g_Q);

    const int nIn = SEQ * ND / 1024;
    const int nW  = ND * ND / 1024;

    split_kernel<<<nIn, 256>>>(q, inqh, inql);
    split_kernel<<<nIn, 256>>>(k, inkh, inkl);
    split_kernel<<<nIn, 256>>>(v, invh, invl);
    split_kernel<<<nW, 256>>>(Wq_w, wqh, wql);
    split_kernel<<<nW, 256>>>(Wk_w, wkh, wkl);
    split_kernel<<<nW, 256>>>(Wv_w, wvh, wvl);
    split_kernel<<<nW, 256>>>(Wo_w, woh, wol);

    dim3 gProj(ND / 64, SEQ / 128);   // (16, 16)
    mm_bias_kernel<<<gProj, 256>>>(inqh, inql, wqh, wql, Wq_b, Qf, Qh, Ql);
    mm_bias_kernel<<<gProj, 256>>>(inkh, inkl, wkh, wkl, Wk_b, nullptr, Kh, Kl);
    mm_bias_kernel<<<gProj, 256>>>(invh, invl, wvh, wvl, Wv_b, nullptr, Vh, Vl);

    li_kernel<<<dim3(SEQ / 64, NH), 256>>>(pos_emb);
    fused_attn_kernel<<<dim3(SEQ / QT, NH), 256, FUSED_SMEM>>>();

    mm_bias_kernel<<<gProj, 256>>>(ctxh, ctxl, woh, wol, Wo_b, out, nullptr, nullptr);
}

// round 8
// speedup vs baseline: 2.6297x; 2.6297x over previous
#include <cuda_runtime.h>
#include <cuda_bf16.h>
#include <math.h>
#include <stdint.h>

#define SEQ   2048
#define ND    1024
#define NH    16
#define DH    64
#define NPOS  64

typedef __nv_bfloat16 bf16;
typedef __nv_bfloat162 bf162;

// ---------------- scratch (device globals: allocation-free) ----------------
__device__ float g_Q[SEQ * ND];                       // fp32 Q (li_kernel)
__device__ float g_logits[(size_t)NH * SEQ * SEQ];    // 256 MB fp32 logits
__device__ float g_li[NH * SEQ * NPOS];

__device__ bf16 g_inqh[SEQ * ND], g_inql[SEQ * ND];
__device__ bf16 g_inkh[SEQ * ND], g_inkl[SEQ * ND];
__device__ bf16 g_invh[SEQ * ND], g_invl[SEQ * ND];
__device__ bf16 g_wqh[ND * ND], g_wql[ND * ND];
__device__ bf16 g_wkh[ND * ND], g_wkl[ND * ND];
__device__ bf16 g_wvh[ND * ND], g_wvl[ND * ND];
__device__ bf16 g_woh[ND * ND], g_wol[ND * ND];
__device__ bf16 g_Qh[SEQ * ND], g_Ql[SEQ * ND];
__device__ bf16 g_Kh[SEQ * ND], g_Kl[SEQ * ND];
__device__ bf16 g_Vh[SEQ * ND], g_Vl[SEQ * ND];
__device__ bf16 g_ctxh[SEQ * ND], g_ctxl[SEQ * ND];
__device__ bf16 g_Sh[(size_t)NH * SEQ * SEQ];         // scores hi
__device__ bf16 g_Sl[(size_t)NH * SEQ * SEQ];         // scores lo

// ---------------- PTX helpers ----------------------------------------------
__device__ __forceinline__ uint32_t smem_u32(const void* p) {
    return (uint32_t)__cvta_generic_to_shared(p);
}
__device__ __forceinline__ void ldsm4(uint32_t* r, uint32_t a) {
    asm volatile("ldmatrix.sync.aligned.m8n8.x4.shared.b16 {%0,%1,%2,%3}, [%4];"
                 : "=r"(r[0]), "=r"(r[1]), "=r"(r[2]), "=r"(r[3]) : "r"(a));
}
__device__ __forceinline__ void ldsm4t(uint32_t* r, uint32_t a) {
    asm volatile("ldmatrix.sync.aligned.m8n8.x4.trans.shared.b16 {%0,%1,%2,%3}, [%4];"
                 : "=r"(r[0]), "=r"(r[1]), "=r"(r[2]), "=r"(r[3]) : "r"(a));
}
__device__ __forceinline__ void mma16816(float* c, const uint32_t* a, const uint32_t* b) {
    asm volatile(
        "mma.sync.aligned.m16n8k16.row.col.f32.bf16.bf16.f32 "
        "{%0,%1,%2,%3}, {%4,%5,%6,%7}, {%8,%9}, {%0,%1,%2,%3};"
        : "+f"(c[0]), "+f"(c[1]), "+f"(c[2]), "+f"(c[3])
        : "r"(a[0]), "r"(a[1]), "r"(a[2]), "r"(a[3]), "r"(b[0]), "r"(b[1]));
}

// ---------------- split fp32 -> bf16 hi + bf16 lo ---------------------------
__global__ __launch_bounds__(256) void split_kernel(
    const float* __restrict__ s, bf16* __restrict__ hi, bf16* __restrict__ lo)
{
    int i = (blockIdx.x * 256 + threadIdx.x) * 4;
    float4 v = *(const float4*)&s[i];
    bf16 h0 = __float2bfloat16_rn(v.x), h1 = __float2bfloat16_rn(v.y);
    bf16 h2 = __float2bfloat16_rn(v.z), h3 = __float2bfloat16_rn(v.w);
    bf16 l0 = __float2bfloat16_rn(v.x - __bfloat162float(h0));
    bf16 l1 = __float2bfloat16_rn(v.y - __bfloat162float(h1));
    bf16 l2 = __float2bfloat16_rn(v.z - __bfloat162float(h2));
    bf16 l3 = __float2bfloat16_rn(v.w - __bfloat162float(h3));
    *(bf162*)&hi[i]     = bf162{h0, h1};
    *(bf162*)&hi[i + 2] = bf162{h2, h3};
    *(bf162*)&lo[i]     = bf162{l0, l1};
    *(bf162*)&lo[i + 2] = bf162{l2, l3};
}

// ---------------- Y = X @ W^T + bias (split-bf16 MMA) -----------------------
// Block 128x128, BK=32, 8 warps (warp tile 32x64), register-prefetch pipeline.
#define KST 40   // 32 + 8 pad

__global__ __launch_bounds__(256) void mm_bias_kernel(
    const bf16* __restrict__ Xh, const bf16* __restrict__ Xl,
    const bf16* __restrict__ Wh, const bf16* __restrict__ Wl,
    const float* __restrict__ bias,
    float* __restrict__ Yf, bf16* __restrict__ Yh, bf16* __restrict__ Yl)
{
    __shared__ bf16 Xsh[128][KST], Xsl[128][KST];
    __shared__ bf16 Wsh[128][KST], Wsl[128][KST];
    const int tid = threadIdx.x, lane = tid & 31, warp = tid >> 5;
    const int wm = warp & 3, wn = warp >> 2;        // 4 x 2 warps, tile 32x64
    const int m0 = blockIdx.y * 128, n0 = blockIdx.x * 128;

    const int xr = tid >> 2, xc = (tid & 3) * 8;    // loader: 64 rows x 32 cols/pass

    uint4 pXh[2], pXl[2], pWh[2], pWl[2];

    #define MM_LOADG(kt)                                                         \
        { _Pragma("unroll") for (int it = 0; it < 2; it++) {                     \
            int r = xr + it * 64;                                                \
            pXh[it] = *(const uint4*)&Xh[(size_t)(m0 + r) * ND + (kt) + xc];     \
            pXl[it] = *(const uint4*)&Xl[(size_t)(m0 + r) * ND + (kt) + xc];     \
            pWh[it] = *(const uint4*)&Wh[(size_t)(n0 + r) * ND + (kt) + xc];     \
            pWl[it] = *(const uint4*)&Wl[(size_t)(n0 + r) * ND + (kt) + xc];     \
        } }
    #define MM_STORES()                                                          \
        { _Pragma("unroll") for (int it = 0; it < 2; it++) {                     \
            int r = xr + it * 64;                                                \
            *(uint4*)&Xsh[r][xc] = pXh[it]; *(uint4*)&Xsl[r][xc] = pXl[it];      \
            *(uint4*)&Wsh[r][xc] = pWh[it]; *(uint4*)&Wsl[r][xc] = pWl[it];      \
        } }

    float acc[2][8][4] = {};
    MM_LOADG(0); MM_STORES(); __syncthreads();

    for (int kt = 32; kt <= ND; kt += 32) {
        const bool more = (kt < ND);
        if (more) MM_LOADG(kt);
        #pragma unroll
        for (int kk = 0; kk < 32; kk += 16) {
            uint32_t Ah[2][4], Al[2][4];
            int arow = wm * 32 + (lane & 7) + ((lane >> 3) & 1) * 8;
            int acol = kk + (lane >> 4) * 8;
            ldsm4(Ah[0], smem_u32(&Xsh[arow][acol]));
            ldsm4(Ah[1], smem_u32(&Xsh[arow + 16][acol]));
            ldsm4(Al[0], smem_u32(&Xsl[arow][acol]));
            ldsm4(Al[1], smem_u32(&Xsl[arow + 16][acol]));
            #pragma unroll
            for (int nt2 = 0; nt2 < 4; nt2++) {
                uint32_t Bh[4], Bl[4];
                int brow = wn * 64 + nt2 * 16 + (lane >> 4) * 8 + (lane & 7);
                int bcol = kk + ((lane >> 3) & 1) * 8;
                ldsm4(Bh, smem_u32(&Wsh[brow][bcol]));
                ldsm4(Bl, smem_u32(&Wsl[brow][bcol]));
                #pragma unroll
                for (int mt = 0; mt < 2; mt++)
                    #pragma unroll
                    for (int p = 0; p < 2; p++) {
                        mma16816(acc[mt][nt2 * 2 + p], Ah[mt], &Bh[p * 2]);
                        mma16816(acc[mt][nt2 * 2 + p], Ah[mt], &Bl[p * 2]);
                        mma16816(acc[mt][nt2 * 2 + p], Al[mt], &Bh[p * 2]);
                    }
            }
        }
        __syncthreads();
        if (more) { MM_STORES(); __syncthreads(); }
    }

    const int r0 = lane >> 2, cc = (lane & 3) * 2;
    #pragma unroll
    for (int mt = 0; mt < 2; mt++)
        #pragma unroll
        for (int nt = 0; nt < 8; nt++) {
            int m = m0 + wm * 32 + mt * 16 + r0;
            int n = n0 + wn * 64 + nt * 8 + cc;
            float b0 = bias[n], b1 = bias[n + 1];
            float v0 = acc[mt][nt][0] + b0, v1 = acc[mt][nt][1] + b1;
            float v2 = acc[mt][nt][2] + b0, v3 = acc[mt][nt][3] + b1;
            if (Yf) {
                *(float2*)&Yf[(size_t)m * ND + n]       = float2{v0, v1};
                *(float2*)&Yf[(size_t)(m + 8) * ND + n] = float2{v2, v3};
            }
            if (Yh) {
                bf16 h0 = __float2bfloat16_rn(v0), h1 = __float2bfloat16_rn(v1);
                bf16 h2 = __float2bfloat16_rn(v2), h3 = __float2bfloat16_rn(v3);
                *(bf162*)&Yh[(size_t)m * ND + n]       = bf162{h0, h1};
                *(bf162*)&Yh[(size_t)(m + 8) * ND + n] = bf162{h2, h3};
                *(bf162*)&Yl[(size_t)m * ND + n] =
                    bf162{__float2bfloat16_rn(v0 - __bfloat162float(h0)),
                          __float2bfloat16_rn(v1 - __bfloat162float(h1))};
                *(bf162*)&Yl[(size_t)(m + 8) * ND + n] =
                    bf162{__float2bfloat16_rn(v2 - __bfloat162float(h2)),
                          __float2bfloat16_rn(v3 - __bfloat162float(h3))};
            }
        }
}

// ---------------- logits = 0.125 * Q K^T (per head) -------------------------
// Block 128(q) x 128(keys), whole DH=64 resident, warp tile 32x64. Dyn smem.
#define QKS 72   // 64 + 8 pad
#define QK_QH 0
#define QK_QL (QK_QH + 128 * QKS * 2)
#define QK_KH (QK_QL + 128 * QKS * 2)
#define QK_KL (QK_KH + 128 * QKS * 2)
#define QK_SMEM (QK_KL + 128 * QKS * 2)

__global__ __launch_bounds__(256) void qk_kernel()
{
    extern __shared__ char sm[];
    bf16* Qsh = (bf16*)(sm + QK_QH);
    bf16* Qsl = (bf16*)(sm + QK_QL);
    bf16* Ksh = (bf16*)(sm + QK_KH);
    bf16* Ksl = (bf16*)(sm + QK_KL);

    const int tid = threadIdx.x, lane = tid & 31, warp = tid >> 5;
    const int wm = warp & 3, wn = warp >> 2;
    const int h = blockIdx.z;
    const int q0 = blockIdx.y * 128, k0 = blockIdx.x * 128;
    const int ho = h * DH;

    const int lr = tid >> 2, lc = (tid & 3) * 16;   // 64 rows x 64 cols in 2 vecs
    #pragma unroll
    for (int it = 0; it < 2; it++) {
        int r = lr + it * 64;
        *(uint4*)&Qsh[r * QKS + lc]     = *(const uint4*)&g_Qh[(size_t)(q0 + r) * ND + ho + lc];
        *(uint4*)&Qsh[r * QKS + lc + 8] = *(const uint4*)&g_Qh[(size_t)(q0 + r) * ND + ho + lc + 8];
        *(uint4*)&Qsl[r * QKS + lc]     = *(const uint4*)&g_Ql[(size_t)(q0 + r) * ND + ho + lc];
        *(uint4*)&Qsl[r * QKS + lc + 8] = *(const uint4*)&g_Ql[(size_t)(q0 + r) * ND + ho + lc + 8];
        *(uint4*)&Ksh[r * QKS + lc]     = *(const uint4*)&g_Kh[(size_t)(k0 + r) * ND + ho + lc];
        *(uint4*)&Ksh[r * QKS + lc + 8] = *(const uint4*)&g_Kh[(size_t)(k0 + r) * ND + ho + lc + 8];
        *(uint4*)&Ksl[r * QKS + lc]     = *(const uint4*)&g_Kl[(size_t)(k0 + r) * ND + ho + lc];
        *(uint4*)&Ksl[r * QKS + lc + 8] = *(const uint4*)&g_Kl[(size_t)(k0 + r) * ND + ho + lc + 8];
    }
    __syncthreads();

    float acc[2][8][4] = {};
    #pragma unroll
    for (int kk = 0; kk < 64; kk += 16) {
        uint32_t Ah[2][4], Al[2][4];
        int arow = wm * 32 + (lane & 7) + ((lane >> 3) & 1) * 8;
        int acol = kk + (lane >> 4) * 8;
        ldsm4(Ah[0], smem_u32(&Qsh[arow * QKS + acol]));
        ldsm4(Ah[1], smem_u32(&Qsh[(arow + 16) * QKS + acol]));
        ldsm4(Al[0], smem_u32(&Qsl[arow * QKS + acol]));
        ldsm4(Al[1], smem_u32(&Qsl[(arow + 16) * QKS + acol]));
        #pragma unroll
        for (int nt2 = 0; nt2 < 4; nt2++) {
            uint32_t Bh[4], Bl[4];
            int brow = wn * 64 + nt2 * 16 + (lane >> 4) * 8 + (lane & 7);
            int bcol = kk + ((lane >> 3) & 1) * 8;
            ldsm4(Bh, smem_u32(&Ksh[brow * QKS + bcol]));
            ldsm4(Bl, smem_u32(&Ksl[brow * QKS + bcol]));
            #pragma unroll
            for (int mt = 0; mt < 2; mt++)
                #pragma unroll
                for (int p = 0; p < 2; p++) {
                    mma16816(acc[mt][nt2 * 2 + p], Ah[mt], &Bh[p * 2]);
                    mma16816(acc[mt][nt2 * 2 + p], Ah[mt], &Bl[p * 2]);
                    mma16816(acc[mt][nt2 * 2 + p], Al[mt], &Bh[p * 2]);
                }
        }
    }

    float* out = g_logits + (size_t)h * SEQ * SEQ;
    const int r0 = lane >> 2, cc = (lane & 3) * 2;
    #pragma unroll
    for (int mt = 0; mt < 2; mt++)
        #pragma unroll
        for (int nt = 0; nt < 8; nt++) {
            int m = q0 + wm * 32 + mt * 16 + r0;
            int n = k0 + wn * 64 + nt * 8 + cc;
            *(float2*)&out[(size_t)m * SEQ + n] =
                float2{acc[mt][nt][0] * 0.125f, acc[mt][nt][1] * 0.125f};
            *(float2*)&out[(size_t)(m + 8) * SEQ + n] =
                float2{acc[mt][nt][2] * 0.125f, acc[mt][nt][3] * 0.125f};
        }
}

// -------- li[h,q,n] = sum_d Q[q, h*64+d] * pos_emb[d, n] --------------------
__global__ __launch_bounds__(256) void li_kernel(const float* __restrict__ pos_emb)
{
    __shared__ float Qs[64][65];
    __shared__ float Ps[64][65];
    const int tid = threadIdx.x;
    const int tx = tid & 15, ty = tid >> 4;
    const int h = blockIdx.y;
    const int q0 = blockIdx.x * 64;

    for (int i = tid; i < 64 * 64; i += 256) {
        int r = i >> 6, c = i & 63;
        Qs[r][c] = g_Q[(q0 + r) * ND + h * DH + c];
        Ps[r][c] = pos_emb[r * NPOS + c];
    }
    __syncthreads();

    float acc[4][4] = {};
    #pragma unroll 8
    for (int d = 0; d < 64; d++) {
        float a[4], b[4];
        #pragma unroll
        for (int i = 0; i < 4; i++) a[i] = Qs[ty * 4 + i][d];
        #pragma unroll
        for (int j = 0; j < 4; j++) b[j] = Ps[d][tx * 4 + j];
        #pragma unroll
        for (int i = 0; i < 4; i++)
            #pragma unroll
            for (int j = 0; j < 4; j++) acc[i][j] += a[i] * b[j];
    }
    #pragma unroll
    for (int i = 0; i < 4; i++)
        #pragma unroll
        for (int j = 0; j < 4; j++)
            g_li[(h * SEQ + q0 + ty * 4 + i) * NPOS + tx * 4 + j] = acc[i][j];
}

// -------- per (h,q) row: gates -> suffix-cumsum -> CoPE -> softmax ----------
__global__ __launch_bounds__(256) void cope_softmax_kernel()
{
    __shared__ float li[NPOS];
    __shared__ float wsum[8];
    __shared__ float redm[8];
    __shared__ float reds[8];

    const int tid = threadIdx.x;
    const int lane = tid & 31, warp = tid >> 5;
    const int q = blockIdx.x, h = blockIdx.y;
    const size_t rbase = ((size_t)h * SEQ + q) * SEQ;
    const float* lrow = g_logits + rbase;

    if (tid < NPOS) li[tid] = g_li[(h * SEQ + q) * NPOS + tid];

    const int base = tid * 8;
    float x[8];
    *(float4*)&x[0] = *(const float4*)&lrow[base];
    *(float4*)&x[4] = *(const float4*)&lrow[base + 4];

    float g[8];
    float csum = 0.0f;
    #pragma unroll
    for (int j = 7; j >= 0; --j) {
        float t;
        asm("tanh.approx.f32 %0, %1;" : "=f"(t) : "f"(x[j] * 0.5f));
        csum += fmaf(t, 0.5f, 0.5f);
        g[j] = csum;
    }
    float v = csum;
    #pragma unroll
    for (int d = 1; d < 32; d <<= 1) {
        float n = __shfl_up_sync(0xffffffffu, v, d);
        if (lane >= d) v += n;
    }
    if (lane == 31) wsum[warp] = v;
    __syncthreads();
    float wpre = 0.0f, total = 0.0f;
    #pragma unroll
    for (int w = 0; w < 8; w++) {
        float s = wsum[w];
        if (w < warp) wpre += s;
        total += s;
    }
    const float off = total - (wpre + v);

    float lmax = -INFINITY;
    #pragma unroll
    for (int j = 0; j < 8; j++) {
        float pos = fminf(g[j] + off, (float)(NPOS - 1));
        float pf = floorf(pos);
        int fi = (int)pf;
        int ci = (int)ceilf(pos);
        float w = pos - pf;
        x[j] += li[ci] * w + li[fi] * (1.0f - w);
        lmax = fmaxf(lmax, x[j]);
    }
    #pragma unroll
    for (int d = 16; d > 0; d >>= 1)
        lmax = fmaxf(lmax, __shfl_xor_sync(0xffffffffu, lmax, d));
    if (lane == 0) redm[warp] = lmax;
    __syncthreads();
    float mx = redm[0];
    #pragma unroll
    for (int w = 1; w < 8; w++) mx = fmaxf(mx, redm[w]);

    float lsum = 0.0f;
    #pragma unroll
    for (int j = 0; j < 8; j++) {
        x[j] = __expf(x[j] - mx);
        lsum += x[j];
    }
    #pragma unroll
    for (int d = 16; d > 0; d >>= 1)
        lsum += __shfl_xor_sync(0xffffffffu, lsum, d);
    if (lane == 0) reds[warp] = lsum;
    __syncthreads();
    float tsum = 0.0f;
    #pragma unroll
    for (int w = 0; w < 8; w++) tsum += reds[w];
    const float inv = 1.0f / tsum;

    bf16* sh = g_Sh + rbase + base;
    bf16* sl = g_Sl + rbase + base;
    #pragma unroll
    for (int jp = 0; jp < 4; jp++) {
        float a = x[2 * jp] * inv, b = x[2 * jp + 1] * inv;
        bf16 ha = __float2bfloat16_rn(a), hb = __float2bfloat16_rn(b);
        ((bf162*)sh)[jp] = bf162{ha, hb};
        ((bf162*)sl)[jp] = bf162{__float2bfloat16_rn(a - __bfloat162float(ha)),
                                 __float2bfloat16_rn(b - __bfloat162float(hb))};
    }
}

// -------- ctx[q, h*64+n] = sum_k scores[h,q,k] * V[k, h*64+n] ---------------
// Block 256(q) x 64(n), BK=32, 8 warps (warp tile 32x64), reg-prefetch. Dyn smem.
#define VST 72
#define CX_SH 0
#define CX_SL (CX_SH + 256 * KST * 2)
#define CX_VH (CX_SL + 256 * KST * 2)
#define CX_VL (CX_VH + 32 * VST * 2)
#define CX_SMEM (CX_VL + 32 * VST * 2)

__global__ __launch_bounds__(256) void ctx_kernel()
{
    extern __shared__ char sm[];
    bf16* Ssh = (bf16*)(sm + CX_SH);
    bf16* Ssl = (bf16*)(sm + CX_SL);
    bf16* Vsh = (bf16*)(sm + CX_VH);
    bf16* Vsl = (bf16*)(sm + CX_VL);

    const int tid = threadIdx.x, lane = tid & 31, warp = tid >> 5;
    const int h = blockIdx.y;
    const int q0 = blockIdx.x * 256;
    const int ho = h * DH;
    const bf16* Sh = g_Sh + (size_t)h * SEQ * SEQ;
    const bf16* Sl = g_Sl + (size_t)h * SEQ * SEQ;

    const int sr = tid >> 1, sc = (tid & 1) * 16;   // S: 128 rows x 2 passes, 16 cols
    const int vr = tid >> 3, vc = (tid & 7) * 8;    // V: 32 rows x 64 cols

    uint4 pSh[2][2], pSl[2][2], pVh, pVl;

    #define CX_LOADG(kt)                                                          \
        { _Pragma("unroll") for (int it = 0; it < 2; it++) {                      \
            int r = sr + it * 128;                                               \
            pSh[it][0] = *(const uint4*)&Sh[(size_t)(q0 + r) * SEQ + (kt) + sc];      \
            pSh[it][1] = *(const uint4*)&Sh[(size_t)(q0 + r) * SEQ + (kt) + sc + 8];  \
            pSl[it][0] = *(const uint4*)&Sl[(size_t)(q0 + r) * SEQ + (kt) + sc];      \
            pSl[it][1] = *(const uint4*)&Sl[(size_t)(q0 + r) * SEQ + (kt) + sc + 8];  \
        }                                                                         \
        pVh = *(const uint4*)&g_Vh[(size_t)((kt) + vr) * ND + ho + vc];           \
        pVl = *(const uint4*)&g_Vl[(size_t)((kt) + vr) * ND + ho + vc]; }
    #define CX_STORES()                                                           \
        { _Pragma("unroll") for (int it = 0; it < 2; it++) {                      \
            int r = sr + it * 128;                                               \
            *(uint4*)&Ssh[r * KST + sc]     = pSh[it][0];                         \
            *(uint4*)&Ssh[r * KST + sc + 8] = pSh[it][1];                         \
            *(uint4*)&Ssl[r * KST + sc]     = pSl[it][0];                         \
            *(uint4*)&Ssl[r * KST + sc + 8] = pSl[it][1];                         \
        }                                                                         \
        *(uint4*)&Vsh[vr * VST + vc] = pVh;                                       \
        *(uint4*)&Vsl[vr * VST + vc] = pVl; }

    float acc[2][8][4] = {};
    CX_LOADG(0); CX_STORES(); __syncthreads();

    for (int kt = 32; kt <= SEQ; kt += 32) {
        const bool more = (kt < SEQ);
        if (more) CX_LOADG(kt);
        #pragma unroll
        for (int kk = 0; kk < 32; kk += 16) {
            uint32_t Ah[2][4], Al[2][4];
            int arow = warp * 32 + (lane & 7) + ((lane >> 3) & 1) * 8;
            int acol = kk + (lane >> 4) * 8;
            ldsm4(Ah[0], smem_u32(&Ssh[arow * KST + acol]));
            ldsm4(Ah[1], smem_u32(&Ssh[(arow + 16) * KST + acol]));
            ldsm4(Al[0], smem_u32(&Ssl[arow * KST + acol]));
            ldsm4(Al[1], smem_u32(&Ssl[(arow + 16) * KST + acol]));
            #pragma unroll
            for (int nt2 = 0; nt2 < 4; nt2++) {
                uint32_t Bh[4], Bl[4];
                int vrow = kk + ((lane >> 3) & 1) * 8 + (lane & 7);
                int vcol = nt2 * 16 + (lane >> 4) * 8;
                ldsm4t(Bh, smem_u32(&Vsh[vrow * VST + vcol]));
                ldsm4t(Bl, smem_u32(&Vsl[vrow * VST + vcol]));
                #pragma unroll
                for (int mt = 0; mt < 2; mt++)
                    #pragma unroll
                    for (int p = 0; p < 2; p++) {
                        mma16816(acc[mt][nt2 * 2 + p], Ah[mt], &Bh[p * 2]);
                        mma16816(acc[mt][nt2 * 2 + p], Ah[mt], &Bl[p * 2]);
                        mma16816(acc[mt][nt2 * 2 + p], Al[mt], &Bh[p * 2]);
                    }
            }
        }
        __syncthreads();
        if (more) { CX_STORES(); __syncthreads(); }
    }

    const int r0 = lane >> 2, cc = (lane & 3) * 2;
    #pragma unroll
    for (int mt = 0; mt < 2; mt++)
        #pragma unroll
        for (int nt = 0; nt < 8; nt++) {
            int m = q0 + warp * 32 + mt * 16 + r0;
            int n = ho + nt * 8 + cc;
            float v0 = acc[mt][nt][0], v1 = acc[mt][nt][1];
            float v2 = acc[mt][nt][2], v3 = acc[mt][nt][3];
            bf16 h0 = __float2bfloat16_rn(v0), h1 = __float2bfloat16_rn(v1);
            bf16 h2 = __float2bfloat16_rn(v2), h3 = __float2bfloat16_rn(v3);
            *(bf162*)&g_ctxh[(size_t)m * ND + n]       = bf162{h0, h1};
            *(bf162*)&g_ctxh[(size_t)(m + 8) * ND + n] = bf162{h2, h3};
            *(bf162*)&g_ctxl[(size_t)m * ND + n] =
                bf162{__float2bfloat16_rn(v0 - __bfloat162float(h0)),
                      __float2bfloat16_rn(v1 - __bfloat162float(h1))};
            *(bf162*)&g_ctxl[(size_t)(m + 8) * ND + n] =
                bf162{__float2bfloat16_rn(v2 - __bfloat162float(h2)),
                      __float2bfloat16_rn(v3 - __bfloat162float(h3))};
        }
}

// ---------------------------------------------------------------------------
extern "C" void kernel_launch(void* const* d_in, const int* in_sizes, int n_in,
                              void* d_out, int out_size)
{
    const float* q      = (const float*)d_in[0];
    const float* k      = (const float*)d_in[1];
    const float* v      = (const float*)d_in[2];
    const float* Wq_w   = (const float*)d_in[3];
    const float* Wq_b   = (const float*)d_in[4];
    const float* Wk_w   = (const float*)d_in[5];
    const float* Wk_b   = (const float*)d_in[6];
    const float* Wv_w   = (const float*)d_in[7];
    const float* Wv_b   = (const float*)d_in[8];
    const float* Wo_w   = (const float*)d_in[9];
    const float* Wo_b   = (const float*)d_in[10];
    const float* pos_emb= (const float*)d_in[11];
    float* out = (float*)d_out;

    static bool attr_set = false;
    if (!attr_set) {
        cudaFuncSetAttribute(qk_kernel,
                             cudaFuncAttributeMaxDynamicSharedMemorySize, QK_SMEM);
        cudaFuncSetAttribute(ctx_kernel,
                             cudaFuncAttributeMaxDynamicSharedMemorySize, CX_SMEM);
        attr_set = true;
    }

    bf16 *inqh, *inql, *inkh, *inkl, *invh, *invl;
    bf16 *wqh, *wql, *wkh, *wkl, *wvh, *wvl, *woh, *wol;
    bf16 *Qh, *Ql, *Kh, *Kl, *Vh, *Vl, *ctxh, *ctxl;
    float* Qf;
    cudaGetSymbolAddress((void**)&inqh, g_inqh); cudaGetSymbolAddress((void**)&inql, g_inql);
    cudaGetSymbolAddress((void**)&inkh, g_inkh); cudaGetSymbolAddress((void**)&inkl, g_inkl);
    cudaGetSymbolAddress((void**)&invh, g_invh); cudaGetSymbolAddress((void**)&invl, g_invl);
    cudaGetSymbolAddress((void**)&wqh, g_wqh);   cudaGetSymbolAddress((void**)&wql, g_wql);
    cudaGetSymbolAddress((void**)&wkh, g_wkh);   cudaGetSymbolAddress((void**)&wkl, g_wkl);
    cudaGetSymbolAddress((void**)&wvh, g_wvh);   cudaGetSymbolAddress((void**)&wvl, g_wvl);
    cudaGetSymbolAddress((void**)&woh, g_woh);   cudaGetSymbolAddress((void**)&wol, g_wol);
    cudaGetSymbolAddress((void**)&Qh, g_Qh);     cudaGetSymbolAddress((void**)&Ql, g_Ql);
    cudaGetSymbolAddress((void**)&Kh, g_Kh);     cudaGetSymbolAddress((void**)&Kl, g_Kl);
    cudaGetSymbolAddress((void**)&Vh, g_Vh);     cudaGetSymbolAddress((void**)&Vl, g_Vl);
    cudaGetSymbolAddress((void**)&ctxh, g_ctxh); cudaGetSymbolAddress((void**)&ctxl, g_ctxl);
    cudaGetSymbolAddress((void**)&Qf, g_Q);

    const int nIn = SEQ * ND / 1024;
    const int nW  = ND * ND / 1024;

    split_kernel<<<nIn, 256>>>(q, inqh, inql);
    split_kernel<<<nIn, 256>>>(k, inkh, inkl);
    split_kernel<<<nIn, 256>>>(v, invh, invl);
    split_kernel<<<nW, 256>>>(Wq_w, wqh, wql);
    split_kernel<<<nW, 256>>>(Wk_w, wkh, wkl);
    split_kernel<<<nW, 256>>>(Wv_w, wvh, wvl);
    split_kernel<<<nW, 256>>>(Wo_w, woh, wol);

    dim3 gProj(ND / 128, SEQ / 128);   // (8, 16)
    mm_bias_kernel<<<gProj, 256>>>(inqh, inql, wqh, wql, Wq_b, Qf, Qh, Ql);
    mm_bias_kernel<<<gProj, 256>>>(inkh, inkl, wkh, wkl, Wk_b, nullptr, Kh, Kl);
    mm_bias_kernel<<<gProj, 256>>>(invh, invl, wvh, wvl, Wv_b, nullptr, Vh, Vl);

    qk_kernel<<<dim3(SEQ / 128, SEQ / 128, NH), 256, QK_SMEM>>>();
    li_kernel<<<dim3(SEQ / 64, NH), 256>>>(pos_emb);
    cope_softmax_kernel<<<dim3(SEQ, NH), 256>>>();
    ctx_kernel<<<dim3(SEQ / 256, NH), 256, CX_SMEM>>>();

    mm_bias_kernel<<<gProj, 256>>>(ctxh, ctxl, woh, wol, Wo_b, out, nullptr, nullptr);
}